// round 2
// baseline (speedup 1.0000x reference)
#include <cuda_runtime.h>
#include <cuda_bf16.h>
#include <math.h>
#include <stdint.h>

// ---------------- problem constants ----------------
#define B 128
#define S_SRC 128
#define S_TRG 64
#define H 1024
#define LEXD 300
#define NTD 128
#define CTXD 300
#define ATT 100
#define ANS 556

// ---------------- scratch ----------------
__device__ float g_srcemb[(size_t)S_SRC * B * LEXD];   // row = s*B+b
__device__ float g_ansemb[(size_t)S_TRG * B * ANS];    // row = t*B+b
__device__ float g_encpre[(size_t)S_SRC * B * 4096];   // packed-n layout
__device__ float g_decpre[(size_t)S_TRG * B * 4096];
__device__ float g_srchid[(size_t)B * S_SRC * H];      // row = b*S+s
__device__ float g_qkey[(size_t)B * S_SRC * ATT];
__device__ float g_qval[(size_t)B * S_SRC * CTXD];
__device__ float g_eh0[B * H];
__device__ float g_eh1[B * H];
__device__ float g_ec[B * H];
__device__ float g_dh0[B * H];
__device__ float g_dh1[B * H];
__device__ float g_dc[B * H];
__device__ float g_ctx[B * CTXD];
__device__ float g_tmp[B * 2048];

// ---------------- gather + init ----------------
__global__ void gather_kernel(const int* __restrict__ src_seqs, const int* __restrict__ trg_nt,
                              const int* __restrict__ par_nt, const int* __restrict__ par_lex,
                              const float* __restrict__ lex_emb, const float* __restrict__ nt_emb) {
    const int64_t nse = (int64_t)S_SRC * B * LEXD;
    const int64_t nae = (int64_t)S_TRG * B * ANS;
    int64_t stride = (int64_t)gridDim.x * blockDim.x;
    for (int64_t i = (int64_t)blockIdx.x * blockDim.x + threadIdx.x; i < nse; i += stride) {
        {
            int d = (int)(i % LEXD);
            int r = (int)(i / LEXD);
            int s = r >> 7, b = r & 127;
            g_srcemb[i] = lex_emb[(int64_t)src_seqs[b * S_SRC + s] * LEXD + d];
        }
        if (i < nae) {
            int d = (int)(i % ANS);
            int r = (int)(i / ANS);
            int t = r >> 7, b = r & 127;
            float v;
            if (d < 128)      v = nt_emb[(int64_t)trg_nt[b * S_TRG + t] * NTD + d];
            else if (d < 256) v = nt_emb[(int64_t)par_nt[b * S_TRG + t] * NTD + (d - 128)];
            else              v = lex_emb[(int64_t)par_lex[b * S_TRG + t] * LEXD + (d - 256)];
            g_ansemb[i] = v;
        }
        if (i < B * H) { g_eh0[i] = 0.f; g_ec[i] = 0.f; }
    }
}

// ---------------- mma helpers ----------------
__device__ __forceinline__ void ldmx4(uint32_t addr, uint32_t* r) {
    asm volatile("ldmatrix.sync.aligned.m8n8.x4.shared.b16 {%0,%1,%2,%3}, [%4];"
                 : "=r"(r[0]), "=r"(r[1]), "=r"(r[2]), "=r"(r[3]) : "r"(addr));
}
__device__ __forceinline__ void ldmx2(uint32_t addr, uint32_t* r) {
    asm volatile("ldmatrix.sync.aligned.m8n8.x2.shared.b16 {%0,%1}, [%2];"
                 : "=r"(r[0]), "=r"(r[1]) : "r"(addr));
}
__device__ __forceinline__ void mma16816(float* c, const uint32_t* a, const uint32_t* b) {
    asm volatile("mma.sync.aligned.m16n8k16.row.col.f32.bf16.bf16.f32 "
                 "{%0,%1,%2,%3},{%4,%5,%6,%7},{%8,%9},{%0,%1,%2,%3};"
                 : "+f"(c[0]), "+f"(c[1]), "+f"(c[2]), "+f"(c[3])
                 : "r"(a[0]), "r"(a[1]), "r"(a[2]), "r"(a[3]), "r"(b[0]), "r"(b[1]));
}

struct SM {
    union U {
        struct MM {
            __nv_bfloat16 Ah[128][40];
            __nv_bfloat16 Al[128][40];
            __nv_bfloat16 Wh[64][40];
            __nv_bfloat16 Wl[64][40];
        } mm;
        float zbuf[128][68];
    } u;
};

// ---------------- unified bf16-split tensor-core GEMM ----------------
// C[M,N] = A[M,K] @ Wsel^T (+bias)(+act) OR fused LSTM step epilogue.
// WSEL: 0 plain W1[n][k] (ldW); 1 packed recurrent (Whh + dec ctx cols of Wih);
//       2 packed input (W1[orig][k], ldW).
// EPI: 0 plain store; 1 encoder LSTM; 2 decoder LSTM.
// ACT (EPI0): 0 none, 1 relu, 2 tanh.
template<int WSEL, int EPI, int ACT>
__global__ __launch_bounds__(256) void mma_gemm(
    const float* __restrict__ A1, int ldA1, int K1,
    const float* __restrict__ A2, int ldA2, int K2,
    const float* __restrict__ W1, int ldW, const float* __restrict__ W2,
    int N, int Kreal, int KT,
    const float* __restrict__ bias, const float* __restrict__ add,
    float* __restrict__ C, int ldC,
    const int* __restrict__ lens, int s,
    float* __restrict__ hout, float* __restrict__ cbuf, float* __restrict__ aux)
{
    __shared__ SM sm;
    const int t = threadIdx.x;
    const int lane = t & 31;
    const int w = t >> 5;
    const int wm = w & 1;        // 2 m-tiles of 64
    const int wn = w >> 1;       // 4 n-tiles of 16
    const int mbase = blockIdx.y * 128;
    const int nbase = blockIdx.x * 64;

    const uint32_t sAh = (uint32_t)__cvta_generic_to_shared(&sm.u.mm.Ah[0][0]);
    const uint32_t sAl = (uint32_t)__cvta_generic_to_shared(&sm.u.mm.Al[0][0]);
    const uint32_t sWh = (uint32_t)__cvta_generic_to_shared(&sm.u.mm.Wh[0][0]);
    const uint32_t sWl = (uint32_t)__cvta_generic_to_shared(&sm.u.mm.Wl[0][0]);

    float acc[4][2][4];
#pragma unroll
    for (int a = 0; a < 4; a++)
#pragma unroll
        for (int b2 = 0; b2 < 2; b2++)
#pragma unroll
            for (int r = 0; r < 4; r++) acc[a][b2][r] = 0.f;

    for (int kc = 0; kc < KT; kc++) {
        const int k0 = kc * 32;
        __syncthreads();
        // ---- stage A (fp32 -> bf16 hi/lo) ----
#pragma unroll
        for (int i = 0; i < 16; i++) {
            int idx = i * 256 + t;
            int row = idx >> 5, kk = idx & 31;
            int k = k0 + kk;
            float v = 0.f;
            int gr = mbase + row;
            if (k < K1)            v = A1[(int64_t)gr * ldA1 + k];
            else if (k < K1 + K2)  v = A2[(int64_t)gr * ldA2 + (k - K1)];
            __nv_bfloat16 hv = __float2bfloat16(v);
            sm.u.mm.Ah[row][kk] = hv;
            sm.u.mm.Al[row][kk] = __float2bfloat16(v - __bfloat162float(hv));
        }
        // ---- stage W ----
#pragma unroll
        for (int i = 0; i < 8; i++) {
            int idx = i * 256 + t;
            int r = idx >> 5, kk = idx & 31;
            int k = k0 + kk;
            int n = nbase + r;
            float v = 0.f;
            if (n < N && k < Kreal) {
                if (WSEL == 0) {
                    v = W1[(int64_t)n * ldW + k];
                } else {
                    int orig = (n & 3) * 1024 + (n >> 2);
                    if (WSEL == 2) v = W1[(int64_t)orig * ldW + k];
                    else v = (k < 1024) ? W1[(int64_t)orig * 1024 + k]
                                        : W2[(int64_t)orig * 856 + 556 + (k - 1024)];
                }
            }
            __nv_bfloat16 hv = __float2bfloat16(v);
            sm.u.mm.Wh[r][kk] = hv;
            sm.u.mm.Wl[r][kk] = __float2bfloat16(v - __bfloat162float(hv));
        }
        __syncthreads();
        // ---- 2 x k16 MMA ----
#pragma unroll
        for (int kk16 = 0; kk16 < 32; kk16 += 16) {
            uint32_t bh[2][2], bl[2][2];
#pragma unroll
            for (int nf = 0; nf < 2; nf++) {
                int rowW = wn * 16 + nf * 8 + (lane & 7);
                int kcol = kk16 + ((lane >> 3) & 1) * 8;
                uint32_t off = (uint32_t)(rowW * 40 + kcol) * 2;
                ldmx2(sWh + off, bh[nf]);
                ldmx2(sWl + off, bl[nf]);
            }
#pragma unroll
            for (int mf = 0; mf < 4; mf++) {
                int rowA = wm * 64 + mf * 16 + (lane & 7) + ((lane >> 3) & 1) * 8;
                int kcol = kk16 + ((lane >> 4) & 1) * 8;
                uint32_t off = (uint32_t)(rowA * 40 + kcol) * 2;
                uint32_t ah[4], al[4];
                ldmx4(sAh + off, ah);
                ldmx4(sAl + off, al);
#pragma unroll
                for (int nf = 0; nf < 2; nf++) {
                    mma16816(acc[mf][nf], ah, bh[nf]);
                    mma16816(acc[mf][nf], al, bh[nf]);
                    mma16816(acc[mf][nf], ah, bl[nf]);
                }
            }
        }
    }

    const int g = lane >> 2, t2 = (lane & 3) * 2;

    if (EPI == 0) {
#pragma unroll
        for (int mf = 0; mf < 4; mf++)
#pragma unroll
            for (int nf = 0; nf < 2; nf++)
#pragma unroll
                for (int r = 0; r < 4; r++) {
                    int rowl = wm * 64 + mf * 16 + g + (r >> 1) * 8;
                    int coll = wn * 16 + nf * 8 + t2 + (r & 1);
                    int gn = nbase + coll;
                    if (gn < N) {
                        float v = acc[mf][nf][r];
                        if (bias) v += bias[gn];
                        if (ACT == 1) v = fmaxf(v, 0.f);
                        if (ACT == 2) v = tanhf(v);
                        C[(int64_t)(mbase + rowl) * ldC + gn] = v;
                    }
                }
        return;
    }

    // ---- LSTM epilogue (M=128, gridDim.y=1) ----
    __syncthreads();   // smem reuse: mm -> zbuf
#pragma unroll
    for (int mf = 0; mf < 4; mf++)
#pragma unroll
        for (int nf = 0; nf < 2; nf++)
#pragma unroll
            for (int r = 0; r < 4; r++) {
                int rowl = wm * 64 + mf * 16 + g + (r >> 1) * 8;
                int coll = wn * 16 + nf * 8 + t2 + (r & 1);
                sm.u.zbuf[rowl][coll] = acc[mf][nf][r];
            }
    __syncthreads();

    const int b = t & 127;
    const int jb = (t >> 7) * 8;
#pragma unroll
    for (int jj = jb; jj < jb + 8; jj++) {
        float4 z = *(float4*)&sm.u.zbuf[b][jj * 4];
        const int jglob = blockIdx.x * 16 + jj;
        float4 pre = *(const float4*)&add[(int64_t)b * 4096 + nbase + jj * 4];
        float zi = z.x + pre.x + bias[jglob];
        float zf = z.y + pre.y + bias[1024 + jglob];
        float zg = z.z + pre.z + bias[2048 + jglob];
        float zo = z.w + pre.w + bias[3072 + jglob];
        float cold = cbuf[b * H + jglob];
        float si = 1.f / (1.f + expf(-zi));
        float sf = 1.f / (1.f + expf(-zf));
        float so = 1.f / (1.f + expf(-zo));
        float c2 = sf * cold + si * tanhf(zg);
        float h2 = so * tanhf(c2);
        if (EPI == 1) {
            bool valid = s < lens[b];
            float hold = A1[b * H + jglob];
            hout[b * H + jglob] = valid ? h2 : hold;
            cbuf[b * H + jglob] = valid ? c2 : cold;
            aux[((int64_t)b * S_SRC + s) * H + jglob] = valid ? h2 : 0.f;
        } else {
            hout[b * H + jglob] = h2;
            cbuf[b * H + jglob] = c2;
            aux[((int64_t)b * S_TRG + s) * H + jglob] = h2;
        }
    }
}

// ---------------- per-decoder-step attention ----------------
__global__ __launch_bounds__(128) void attn_kernel(const float* __restrict__ dh,
                                                   const float* __restrict__ Wa,
                                                   const float* __restrict__ ba,
                                                   const int* __restrict__ lens) {
    __shared__ float hs[1024];
    __shared__ float ak[112];
    __shared__ float en[128];
    __shared__ float red[32];
    int b = blockIdx.x;
    int tid = threadIdx.x;
    int lane = tid & 31, wid = tid >> 5;

#pragma unroll
    for (int m = 0; m < 8; m++) hs[m * 128 + tid] = dh[b * H + m * 128 + tid];
    __syncthreads();

    for (int k = wid; k < ATT; k += 4) {
        float p = 0.f;
        const float* wr = Wa + (int64_t)k * H;
#pragma unroll
        for (int m = 0; m < 32; m++) p = fmaf(wr[m * 32 + lane], hs[m * 32 + lane], p);
        for (int o = 16; o; o >>= 1) p += __shfl_xor_sync(0xffffffffu, p, o);
        if (lane == 0) ak[k] = tanhf(p + ba[k]);
    }
    __syncthreads();

    int L = lens[b];
    float e;
    {
        const float* qk = g_qkey + ((int64_t)b * S_SRC + tid) * ATT;
        float p = 0.f;
#pragma unroll 4
        for (int d = 0; d < ATT; d++) p = fmaf(qk[d], ak[d], p);
        e = (tid < L) ? p : -1e9f;
    }
    float mx = e;
    for (int o = 16; o; o >>= 1) mx = fmaxf(mx, __shfl_xor_sync(0xffffffffu, mx, o));
    if (lane == 0) red[wid] = mx;
    __syncthreads();
    mx = fmaxf(fmaxf(red[0], red[1]), fmaxf(red[2], red[3]));
    float ex = expf(e - mx);
    float sm = ex;
    for (int o = 16; o; o >>= 1) sm += __shfl_xor_sync(0xffffffffu, sm, o);
    if (lane == 0) red[8 + wid] = sm;
    __syncthreads();
    sm = red[8] + red[9] + red[10] + red[11];
    en[tid] = ex / sm;
    __syncthreads();

    for (int d = tid; d < CTXD; d += 128) {
        float c = 0.f;
        for (int s2 = 0; s2 < S_SRC; s2++)
            c = fmaf(en[s2], g_qval[((int64_t)b * S_SRC + s2) * CTXD + d], c);
        g_ctx[b * CTXD + d] = c;
    }
}

// ---------------- launcher ----------------
extern "C" void kernel_launch(void* const* d_in, const int* in_sizes, int n_in,
                              void* d_out, int out_size) {
    const int*   src_seqs = (const int*)d_in[0];
    const int*   src_len  = (const int*)d_in[1];
    const int*   trg_nt   = (const int*)d_in[2];
    const int*   par_nt   = (const int*)d_in[3];
    const int*   par_lex  = (const int*)d_in[4];
    const float* lex_emb  = (const float*)d_in[5];
    const float* nt_emb   = (const float*)d_in[6];
    const float* enc_Wih  = (const float*)d_in[7];
    const float* enc_Whh  = (const float*)d_in[8];
    const float* enc_b    = (const float*)d_in[9];
    const float* dec_Wih  = (const float*)d_in[10];
    const float* dec_Whh  = (const float*)d_in[11];
    const float* dec_b    = (const float*)d_in[12];
    const float* Wh1 = (const float*)d_in[13];
    const float* bh1 = (const float*)d_in[14];
    const float* Wh2 = (const float*)d_in[15];
    const float* bh2 = (const float*)d_in[16];
    const float* Wc1 = (const float*)d_in[17];
    const float* bc1 = (const float*)d_in[18];
    const float* Wc2 = (const float*)d_in[19];
    const float* bc2 = (const float*)d_in[20];
    const float* Wa  = (const float*)d_in[21];
    const float* ba  = (const float*)d_in[22];
    const float* Wqk = (const float*)d_in[23];
    const float* bqk = (const float*)d_in[24];
    const float* Wqv = (const float*)d_in[25];
    const float* bqv = (const float*)d_in[26];
    float* out = (float*)d_out;

    float *eh[2], *dh[2], *encpre, *decpre, *srcemb, *ansemb, *srchid, *qkey, *qval, *ec, *dc, *ctx, *tmp;
    cudaGetSymbolAddress((void**)&eh[0], g_eh0);
    cudaGetSymbolAddress((void**)&eh[1], g_eh1);
    cudaGetSymbolAddress((void**)&dh[0], g_dh0);
    cudaGetSymbolAddress((void**)&dh[1], g_dh1);
    cudaGetSymbolAddress((void**)&encpre, g_encpre);
    cudaGetSymbolAddress((void**)&decpre, g_decpre);
    cudaGetSymbolAddress((void**)&srcemb, g_srcemb);
    cudaGetSymbolAddress((void**)&ansemb, g_ansemb);
    cudaGetSymbolAddress((void**)&srchid, g_srchid);
    cudaGetSymbolAddress((void**)&qkey, g_qkey);
    cudaGetSymbolAddress((void**)&qval, g_qval);
    cudaGetSymbolAddress((void**)&ec, g_ec);
    cudaGetSymbolAddress((void**)&dc, g_dc);
    cudaGetSymbolAddress((void**)&ctx, g_ctx);
    cudaGetSymbolAddress((void**)&tmp, g_tmp);

    gather_kernel<<<2048, 256>>>(src_seqs, trg_nt, par_nt, par_lex, lex_emb, nt_emb);

    // input-side precompute (packed-n): encpre = srcemb @ encWih^T, decpre = ansemb @ decWih[:, :556]^T
    mma_gemm<2,0,0><<<dim3(64,128), 256>>>(srcemb, 300, 300, nullptr, 0, 0,
        enc_Wih, 300, nullptr, 4096, 300, 10, nullptr, nullptr, encpre, 4096,
        nullptr, 0, nullptr, nullptr, nullptr);
    mma_gemm<2,0,0><<<dim3(64,64), 256>>>(ansemb, 556, 556, nullptr, 0, 0,
        dec_Wih, 856, nullptr, 4096, 556, 18, nullptr, nullptr, decpre, 4096,
        nullptr, 0, nullptr, nullptr, nullptr);

    // encoder recurrence
    for (int s = 0; s < S_SRC; s++) {
        mma_gemm<1,1,0><<<dim3(64,1), 256>>>(eh[s & 1], H, 1024, nullptr, 0, 0,
            enc_Whh, 1024, nullptr, 4096, 1024, 32, enc_b, encpre + (int64_t)s * B * 4096,
            nullptr, 0, src_len, s, eh[(s + 1) & 1], ec, srchid);
    }
    float* ehT = eh[S_SRC & 1];

    // attention keys/values
    mma_gemm<0,0,2><<<dim3(2,128), 256>>>(srchid, H, 1024, nullptr, 0, 0,
        Wqk, 1024, nullptr, ATT, 1024, 32, bqk, nullptr, qkey, ATT,
        nullptr, 0, nullptr, nullptr, nullptr);
    mma_gemm<0,0,0><<<dim3(5,128), 256>>>(srchid, H, 1024, nullptr, 0, 0,
        Wqv, 1024, nullptr, CTXD, 1024, 32, bqv, nullptr, qval, CTXD,
        nullptr, 0, nullptr, nullptr, nullptr);

    // decoder init MLPs
    mma_gemm<0,0,1><<<dim3(32,1), 256>>>(ehT, H, 1024, nullptr, 0, 0,
        Wh1, 1024, nullptr, 2048, 1024, 32, bh1, nullptr, tmp, 2048,
        nullptr, 0, nullptr, nullptr, nullptr);
    mma_gemm<0,0,0><<<dim3(16,1), 256>>>(tmp, 2048, 2048, nullptr, 0, 0,
        Wh2, 2048, nullptr, 1024, 2048, 64, bh2, nullptr, dh[0], 1024,
        nullptr, 0, nullptr, nullptr, nullptr);
    mma_gemm<0,0,1><<<dim3(32,1), 256>>>(ec, H, 1024, nullptr, 0, 0,
        Wc1, 1024, nullptr, 2048, 1024, 32, bc1, nullptr, tmp, 2048,
        nullptr, 0, nullptr, nullptr, nullptr);
    mma_gemm<0,0,0><<<dim3(16,1), 256>>>(tmp, 2048, 2048, nullptr, 0, 0,
        Wc2, 2048, nullptr, 1024, 2048, 64, bc2, nullptr, dc, 1024,
        nullptr, 0, nullptr, nullptr, nullptr);

    // decoder recurrence with attention
    for (int t = 0; t < S_TRG; t++) {
        attn_kernel<<<128, 128>>>(dh[t & 1], Wa, ba, src_len);
        mma_gemm<1,2,0><<<dim3(64,1), 256>>>(dh[t & 1], H, 1024, ctx, CTXD, 300,
            dec_Whh, 1024, dec_Wih, 4096, 1324, 42, dec_b, decpre + (int64_t)t * B * 4096,
            nullptr, 0, src_len, t, dh[(t + 1) & 1], dc, out);
    }
}

// round 3
// speedup vs baseline: 5.4894x; 5.4894x over previous
#include <cuda_runtime.h>
#include <cuda_bf16.h>
#include <math.h>
#include <stdint.h>

// ---------------- problem constants ----------------
#define B 128
#define S_SRC 128
#define S_TRG 64
#define H 1024

#define KE 1024      // enc recurrent K
#define KDR 1344     // dec recurrent K padded (real 1324 = 1024 h + 300 ctx)
#define KSE 320      // src embed K padded (real 300)
#define KAE 576      // ans embed K padded (real 556)

#define SMEMB 92160  // dynamic smem bytes for mma_gemm

// ---------------- bf16 hi/lo weights (converted once per launch) ----------------
__device__ __nv_bfloat16 g_WerH[4096 * KE],  g_WerL[4096 * KE];     // enc recurrent, packed-n
__device__ __nv_bfloat16 g_WdrH[4096 * KDR], g_WdrL[4096 * KDR];    // dec recurrent, packed-n
__device__ __nv_bfloat16 g_WeiH[4096 * KSE], g_WeiL[4096 * KSE];    // enc input, packed-n
__device__ __nv_bfloat16 g_WdiH[4096 * KAE], g_WdiL[4096 * KAE];    // dec input, packed-n
__device__ __nv_bfloat16 g_WqkH[128 * 1024], g_WqkL[128 * 1024];
__device__ __nv_bfloat16 g_WqvH[320 * 1024], g_WqvL[320 * 1024];
__device__ __nv_bfloat16 g_WaH[128 * 1024],  g_WaL[128 * 1024];
__device__ __nv_bfloat16 g_Wh1H[2048 * 1024], g_Wh1L[2048 * 1024];
__device__ __nv_bfloat16 g_Wh2H[1024 * 2048], g_Wh2L[1024 * 2048];
__device__ __nv_bfloat16 g_Wc1H[2048 * 1024], g_Wc1L[2048 * 1024];
__device__ __nv_bfloat16 g_Wc2H[1024 * 2048], g_Wc2L[1024 * 2048];

// ---------------- activations ----------------
__device__ __nv_bfloat16 g_seH[(size_t)S_SRC * B * KSE], g_seL[(size_t)S_SRC * B * KSE];
__device__ __nv_bfloat16 g_aeH[(size_t)S_TRG * B * KAE], g_aeL[(size_t)S_TRG * B * KAE];
__device__ float g_encpre[(size_t)S_SRC * B * 4096];
__device__ float g_decpre[(size_t)S_TRG * B * 4096];
__device__ __nv_bfloat16 g_shH[(size_t)B * S_SRC * H], g_shL[(size_t)B * S_SRC * H];
__device__ float g_qkey[(size_t)B * S_SRC * 112];
__device__ float g_qval[(size_t)B * S_SRC * 304];
__device__ __nv_bfloat16 g_ehH[2 * B * H], g_ehL[2 * B * H];
__device__ __nv_bfloat16 g_dAH[2 * B * KDR], g_dAL[2 * B * KDR];
__device__ float g_ec[B * H], g_dc[B * H];
__device__ __nv_bfloat16 g_ecH[B * H], g_ecL[B * H];
__device__ __nv_bfloat16 g_t1H[B * 2048], g_t1L[B * 2048];
__device__ float g_akey[B * 112];

// ---------------- weight conversion (fp32 -> bf16 hi/lo, padded layouts) ----------------
// mode 0: plain [Nreal][lds] row-major (zero-pad N/K)
// mode 1: packed-n: orig = (n&3)*1024 + (n>>2); src1[orig*lds + k] for k < Kreal
// mode 2: dec recurrent packed: k<1024 -> Whh[orig*1024+k]; k<1324 -> Wih[orig*856+556+(k-1024)]
__global__ void convw_kernel(__nv_bfloat16* dh, __nv_bfloat16* dl,
                             const float* __restrict__ s1, const float* __restrict__ s2,
                             int Npad, int Nreal, int Kpad, int Kreal, int lds, int mode) {
    int64_t tot = (int64_t)Npad * Kpad;
    int64_t stride = (int64_t)gridDim.x * blockDim.x;
    for (int64_t i = (int64_t)blockIdx.x * blockDim.x + threadIdx.x; i < tot; i += stride) {
        int n = (int)(i / Kpad), k = (int)(i % Kpad);
        float v = 0.f;
        if (mode == 0) {
            if (n < Nreal && k < Kreal) v = s1[(int64_t)n * lds + k];
        } else {
            int orig = (n & 3) * 1024 + (n >> 2);
            if (mode == 1) { if (k < Kreal) v = s1[(int64_t)orig * lds + k]; }
            else {
                if (k < 1024) v = s1[(int64_t)orig * 1024 + k];
                else if (k < 1324) v = s2[(int64_t)orig * 856 + 556 + (k - 1024)];
            }
        }
        __nv_bfloat16 hv = __float2bfloat16(v);
        dh[i] = hv;
        dl[i] = __float2bfloat16(v - __bfloat162float(hv));
    }
}

// ---------------- gather embeddings (bf16 hi/lo) + zero states ----------------
__global__ void gather_kernel(const int* __restrict__ src_seqs, const int* __restrict__ trg_nt,
                              const int* __restrict__ par_nt, const int* __restrict__ par_lex,
                              const float* __restrict__ lex_emb, const float* __restrict__ nt_emb) {
    const int64_t nse = (int64_t)S_SRC * B * KSE;   // 5.24M
    const int64_t nae = (int64_t)S_TRG * B * KAE;   // 4.72M
    int64_t stride = (int64_t)gridDim.x * blockDim.x;
    for (int64_t i = (int64_t)blockIdx.x * blockDim.x + threadIdx.x; i < nse; i += stride) {
        {
            int d = (int)(i % KSE);
            int r = (int)(i / KSE);
            int s = r >> 7, b = r & 127;
            float v = (d < 300) ? lex_emb[(int64_t)src_seqs[b * S_SRC + s] * 300 + d] : 0.f;
            __nv_bfloat16 hv = __float2bfloat16(v);
            g_seH[i] = hv;
            g_seL[i] = __float2bfloat16(v - __bfloat162float(hv));
        }
        if (i < nae) {
            int d = (int)(i % KAE);
            int r = (int)(i / KAE);
            int t = r >> 7, b = r & 127;
            float v = 0.f;
            if (d < 128)      v = nt_emb[(int64_t)trg_nt[b * S_TRG + t] * 128 + d];
            else if (d < 256) v = nt_emb[(int64_t)par_nt[b * S_TRG + t] * 128 + (d - 128)];
            else if (d < 556) v = lex_emb[(int64_t)par_lex[b * S_TRG + t] * 300 + (d - 256)];
            __nv_bfloat16 hv = __float2bfloat16(v);
            g_aeH[i] = hv;
            g_aeL[i] = __float2bfloat16(v - __bfloat162float(hv));
        }
        if (i < 2 * B * KDR) { g_dAH[i] = __float2bfloat16(0.f); g_dAL[i] = __float2bfloat16(0.f); }
        if (i < 2 * B * H)   { g_ehH[i] = __float2bfloat16(0.f); g_ehL[i] = __float2bfloat16(0.f); }
        if (i < B * H)       g_ec[i] = 0.f;
    }
}

// ---------------- mma helpers ----------------
__device__ __forceinline__ void ldmx4(uint32_t addr, uint32_t* r) {
    asm volatile("ldmatrix.sync.aligned.m8n8.x4.shared.b16 {%0,%1,%2,%3}, [%4];"
                 : "=r"(r[0]), "=r"(r[1]), "=r"(r[2]), "=r"(r[3]) : "r"(addr));
}
__device__ __forceinline__ void ldmx2(uint32_t addr, uint32_t* r) {
    asm volatile("ldmatrix.sync.aligned.m8n8.x2.shared.b16 {%0,%1}, [%2];"
                 : "=r"(r[0]), "=r"(r[1]) : "r"(addr));
}
__device__ __forceinline__ void mma16816(float* c, const uint32_t* a, const uint32_t* b) {
    asm volatile("mma.sync.aligned.m16n8k16.row.col.f32.bf16.bf16.f32 "
                 "{%0,%1,%2,%3},{%4,%5,%6,%7},{%8,%9},{%0,%1,%2,%3};"
                 : "+f"(c[0]), "+f"(c[1]), "+f"(c[2]), "+f"(c[3])
                 : "r"(a[0]), "r"(a[1]), "r"(a[2]), "r"(a[3]), "r"(b[0]), "r"(b[1]));
}
__device__ __forceinline__ void cpa16(uint32_t dst, const void* src) {
    asm volatile("cp.async.cg.shared.global [%0], [%1], 16;" :: "r"(dst), "l"(src));
}

// smem layout (bf16 elems): A[buf][hl][128][72] then W[buf][hl][32][72] at elem 36864
__device__ __forceinline__ void load_chunk(uint32_t smb, int buf, int t, int k0,
    const __nv_bfloat16* __restrict__ Ah, const __nv_bfloat16* __restrict__ Al, int ldA, int mbase,
    const __nv_bfloat16* __restrict__ Wh, const __nv_bfloat16* __restrict__ Wl, int ldW, int nbase)
{
#pragma unroll
    for (int i = 0; i < 8; i++) {
        int u = i * 256 + t;
        int hl = u >> 10;
        int rem = u & 1023;
        int row = rem >> 3, grp = rem & 7;
        const __nv_bfloat16* src = (hl ? Al : Ah) + (int64_t)(mbase + row) * ldA + k0 + grp * 8;
        uint32_t dst = smb + (uint32_t)(((buf * 2 + hl) * 128 + row) * 72 + grp * 8) * 2u;
        cpa16(dst, src);
    }
#pragma unroll
    for (int i = 0; i < 2; i++) {
        int u = i * 256 + t;
        int hl = u >> 8;
        int rem = u & 255;
        int row = rem >> 3, grp = rem & 7;
        const __nv_bfloat16* src = (hl ? Wl : Wh) + (int64_t)(nbase + row) * ldW + k0 + grp * 8;
        uint32_t dst = smb + (uint32_t)(36864 + ((buf * 2 + hl) * 32 + row) * 72 + grp * 8) * 2u;
        cpa16(dst, src);
    }
    asm volatile("cp.async.commit_group;" ::: "memory");
}

// ---------------- unified pipelined bf16-split tensor-core GEMM ----------------
// Tile: M=128 per grid.y block, N=32 per grid.x block, K chunks of 64, double-buffered.
// OUT: 0 fp32 store (+ACT), 1 bf16 hi/lo store (+ACT), 2 encoder LSTM epi, 3 decoder LSTM epi
template<int OUT, int ACT>
__global__ __launch_bounds__(256) void mma_gemm(
    const __nv_bfloat16* __restrict__ Ah, const __nv_bfloat16* __restrict__ Al, int ldA,
    const __nv_bfloat16* __restrict__ Wh, const __nv_bfloat16* __restrict__ Wl, int ldW,
    int N, int KT,
    const float* __restrict__ bias, const float* __restrict__ add,
    float* __restrict__ Cf, __nv_bfloat16* __restrict__ Ch, __nv_bfloat16* __restrict__ Cl, int ldC,
    const int* __restrict__ lens, int s,
    __nv_bfloat16* __restrict__ houtH, __nv_bfloat16* __restrict__ houtL, int ldHo,
    float* __restrict__ cbuf,
    __nv_bfloat16* __restrict__ auxH, __nv_bfloat16* __restrict__ auxL,
    float* __restrict__ outF)
{
    extern __shared__ char smraw[];
    uint32_t smb = (uint32_t)__cvta_generic_to_shared(smraw);
    const int t = threadIdx.x;
    const int lane = t & 31, w = t >> 5;
    const int wm = w & 3, wn = w >> 2;            // 4 m-subtiles x 2 n-subtiles
    const int mbase = blockIdx.y * 128;
    const int nbase = blockIdx.x * 32;

    float acc[2][2][4];
#pragma unroll
    for (int a = 0; a < 2; a++)
#pragma unroll
        for (int b2 = 0; b2 < 2; b2++)
#pragma unroll
            for (int r = 0; r < 4; r++) acc[a][b2][r] = 0.f;

    load_chunk(smb, 0, t, 0, Ah, Al, ldA, mbase, Wh, Wl, ldW, nbase);

    for (int kc = 0; kc < KT; kc++) {
        const int cur = kc & 1;
        if (kc + 1 < KT) {
            load_chunk(smb, cur ^ 1, t, (kc + 1) * 64, Ah, Al, ldA, mbase, Wh, Wl, ldW, nbase);
            asm volatile("cp.async.wait_group 1;" ::: "memory");
        } else {
            asm volatile("cp.async.wait_group 0;" ::: "memory");
        }
        __syncthreads();
#pragma unroll
        for (int kk16 = 0; kk16 < 64; kk16 += 16) {
            uint32_t bh[2][2], bl[2][2];
#pragma unroll
            for (int nf = 0; nf < 2; nf++) {
                int rowW = wn * 16 + nf * 8 + (lane & 7);
                int kcol = kk16 + ((lane >> 3) & 1) * 8;
                ldmx2(smb + (uint32_t)(36864 + ((cur * 2 + 0) * 32 + rowW) * 72 + kcol) * 2u, bh[nf]);
                ldmx2(smb + (uint32_t)(36864 + ((cur * 2 + 1) * 32 + rowW) * 72 + kcol) * 2u, bl[nf]);
            }
#pragma unroll
            for (int mf = 0; mf < 2; mf++) {
                int rowA = wm * 32 + mf * 16 + (lane & 7) + ((lane >> 3) & 1) * 8;
                int kcol = kk16 + ((lane >> 4) & 1) * 8;
                uint32_t ah[4], al[4];
                ldmx4(smb + (uint32_t)(((cur * 2 + 0) * 128 + rowA) * 72 + kcol) * 2u, ah);
                ldmx4(smb + (uint32_t)(((cur * 2 + 1) * 128 + rowA) * 72 + kcol) * 2u, al);
#pragma unroll
                for (int nf = 0; nf < 2; nf++) {
                    mma16816(acc[mf][nf], ah, bh[nf]);
                    mma16816(acc[mf][nf], al, bh[nf]);
                    mma16816(acc[mf][nf], ah, bl[nf]);
                }
            }
        }
        __syncthreads();
    }

    const int g2 = lane >> 2, q2 = (lane & 3) * 2;

    if (OUT <= 1) {
#pragma unroll
        for (int mf = 0; mf < 2; mf++)
#pragma unroll
            for (int nf = 0; nf < 2; nf++)
#pragma unroll
                for (int r = 0; r < 4; r++) {
                    int row = mbase + wm * 32 + mf * 16 + g2 + (r >> 1) * 8;
                    int col = nbase + wn * 16 + nf * 8 + q2 + (r & 1);
                    if (col < N) {
                        float v = acc[mf][nf][r];
                        if (bias) v += bias[col];
                        if (ACT == 1) v = fmaxf(v, 0.f);
                        if (ACT == 2) v = tanhf(v);
                        if (OUT == 0) Cf[(int64_t)row * ldC + col] = v;
                        else {
                            __nv_bfloat16 hv = __float2bfloat16(v);
                            Ch[(int64_t)row * ldC + col] = hv;
                            Cl[(int64_t)row * ldC + col] = __float2bfloat16(v - __bfloat162float(hv));
                        }
                    }
                }
        return;
    }

    // ---- fused LSTM epilogue (M=128, gridDim.y==1, packed-n: col = j*4+gate) ----
    float* zb = (float*)smraw;   // [128][33]
    __syncthreads();
#pragma unroll
    for (int mf = 0; mf < 2; mf++)
#pragma unroll
        for (int nf = 0; nf < 2; nf++)
#pragma unroll
            for (int r = 0; r < 4; r++) {
                int row = wm * 32 + mf * 16 + g2 + (r >> 1) * 8;
                int col = wn * 16 + nf * 8 + q2 + (r & 1);
                zb[row * 33 + col] = acc[mf][nf][r];
            }
    __syncthreads();

    const int b = t & 127;
    const int jj0 = (t >> 7) * 4;
#pragma unroll
    for (int jj = jj0; jj < jj0 + 4; jj++) {
        const int jglob = (nbase >> 2) + jj;
        float4 pre = *(const float4*)&add[(int64_t)b * 4096 + nbase + jj * 4];
        float zi = zb[b * 33 + jj * 4 + 0] + pre.x + bias[jglob];
        float zf = zb[b * 33 + jj * 4 + 1] + pre.y + bias[1024 + jglob];
        float zg = zb[b * 33 + jj * 4 + 2] + pre.z + bias[2048 + jglob];
        float zo = zb[b * 33 + jj * 4 + 3] + pre.w + bias[3072 + jglob];
        float cold = cbuf[b * H + jglob];
        float si = 1.f / (1.f + expf(-zi));
        float sf = 1.f / (1.f + expf(-zf));
        float so = 1.f / (1.f + expf(-zo));
        float c2 = sf * cold + si * tanhf(zg);
        float h2 = so * tanhf(c2);
        __nv_bfloat16 nh = __float2bfloat16(h2);
        __nv_bfloat16 nl = __float2bfloat16(h2 - __bfloat162float(nh));
        if (OUT == 2) {
            bool valid = s < lens[b];
            if (valid) cbuf[b * H + jglob] = c2;
            houtH[(int64_t)b * ldHo + jglob] = valid ? nh : Ah[(int64_t)b * ldA + jglob];
            houtL[(int64_t)b * ldHo + jglob] = valid ? nl : Al[(int64_t)b * ldA + jglob];
            __nv_bfloat16 z16 = __float2bfloat16(0.f);
            auxH[((int64_t)b * S_SRC + s) * H + jglob] = valid ? nh : z16;
            auxL[((int64_t)b * S_SRC + s) * H + jglob] = valid ? nl : z16;
        } else {
            cbuf[b * H + jglob] = c2;
            houtH[(int64_t)b * ldHo + jglob] = nh;
            houtL[(int64_t)b * ldHo + jglob] = nl;
            outF[((int64_t)b * S_TRG + s) * H + jglob] = h2;
        }
    }
}

// ---------------- attention stage 2: softmax + context ----------------
__global__ __launch_bounds__(128) void attn2_kernel(const int* __restrict__ lens,
                                                    __nv_bfloat16* __restrict__ ctxH,
                                                    __nv_bfloat16* __restrict__ ctxL) {
    __shared__ float ak[112];
    __shared__ float en[128];
    __shared__ float red[8];
    int b = blockIdx.x;
    int tid = threadIdx.x;
    int lane = tid & 31, wid = tid >> 5;

    if (tid < 100) ak[tid] = g_akey[b * 112 + tid];
    __syncthreads();

    int L = lens[b];
    float e;
    {
        const float* qk = &g_qkey[((int64_t)b * S_SRC + tid) * 112];
        float p = 0.f;
#pragma unroll 4
        for (int d = 0; d < 100; d++) p = fmaf(qk[d], ak[d], p);
        e = (tid < L) ? p : -1e9f;
    }
    float mx = e;
    for (int o = 16; o; o >>= 1) mx = fmaxf(mx, __shfl_xor_sync(0xffffffffu, mx, o));
    if (lane == 0) red[wid] = mx;
    __syncthreads();
    mx = fmaxf(fmaxf(red[0], red[1]), fmaxf(red[2], red[3]));
    float ex = expf(e - mx);
    float sm = ex;
    for (int o = 16; o; o >>= 1) sm += __shfl_xor_sync(0xffffffffu, sm, o);
    if (lane == 0) red[4 + wid] = sm;
    __syncthreads();
    sm = red[4] + red[5] + red[6] + red[7];
    en[tid] = ex / sm;
    __syncthreads();

    for (int d = tid; d < 300; d += 128) {
        float c = 0.f;
#pragma unroll 4
        for (int s2 = 0; s2 < S_SRC; s2++)
            c = fmaf(en[s2], g_qval[((int64_t)b * S_SRC + s2) * 304 + d], c);
        __nv_bfloat16 hv = __float2bfloat16(c);
        ctxH[(int64_t)b * KDR + 1024 + d] = hv;
        ctxL[(int64_t)b * KDR + 1024 + d] = __float2bfloat16(c - __bfloat162float(hv));
    }
}

// ---------------- launcher ----------------
extern "C" void kernel_launch(void* const* d_in, const int* in_sizes, int n_in,
                              void* d_out, int out_size) {
    const int*   src_seqs = (const int*)d_in[0];
    const int*   src_len  = (const int*)d_in[1];
    const int*   trg_nt   = (const int*)d_in[2];
    const int*   par_nt   = (const int*)d_in[3];
    const int*   par_lex  = (const int*)d_in[4];
    const float* lex_emb  = (const float*)d_in[5];
    const float* nt_emb   = (const float*)d_in[6];
    const float* enc_Wih  = (const float*)d_in[7];
    const float* enc_Whh  = (const float*)d_in[8];
    const float* enc_b    = (const float*)d_in[9];
    const float* dec_Wih  = (const float*)d_in[10];
    const float* dec_Whh  = (const float*)d_in[11];
    const float* dec_b    = (const float*)d_in[12];
    const float* Wh1 = (const float*)d_in[13];
    const float* bh1 = (const float*)d_in[14];
    const float* Wh2 = (const float*)d_in[15];
    const float* bh2 = (const float*)d_in[16];
    const float* Wc1 = (const float*)d_in[17];
    const float* bc1 = (const float*)d_in[18];
    const float* Wc2 = (const float*)d_in[19];
    const float* bc2 = (const float*)d_in[20];
    const float* Wa  = (const float*)d_in[21];
    const float* ba  = (const float*)d_in[22];
    const float* Wqk = (const float*)d_in[23];
    const float* bqk = (const float*)d_in[24];
    const float* Wqv = (const float*)d_in[25];
    const float* bqv = (const float*)d_in[26];
    float* out = (float*)d_out;

    // opt-in to >48KB dynamic smem (idempotent)
    cudaFuncSetAttribute(mma_gemm<0,0>, cudaFuncAttributeMaxDynamicSharedMemorySize, SMEMB);
    cudaFuncSetAttribute(mma_gemm<0,2>, cudaFuncAttributeMaxDynamicSharedMemorySize, SMEMB);
    cudaFuncSetAttribute(mma_gemm<1,0>, cudaFuncAttributeMaxDynamicSharedMemorySize, SMEMB);
    cudaFuncSetAttribute(mma_gemm<1,1>, cudaFuncAttributeMaxDynamicSharedMemorySize, SMEMB);
    cudaFuncSetAttribute(mma_gemm<2,0>, cudaFuncAttributeMaxDynamicSharedMemorySize, SMEMB);
    cudaFuncSetAttribute(mma_gemm<3,0>, cudaFuncAttributeMaxDynamicSharedMemorySize, SMEMB);

    // device-global pointers
    __nv_bfloat16 *WerH,*WerL,*WdrH,*WdrL,*WeiH,*WeiL,*WdiH,*WdiL;
    __nv_bfloat16 *WqkH,*WqkL,*WqvH,*WqvL,*WaH,*WaL;
    __nv_bfloat16 *Wh1H,*Wh1L,*Wh2H,*Wh2L,*Wc1H,*Wc1L,*Wc2H,*Wc2L;
    __nv_bfloat16 *seH,*seL,*aeH,*aeL,*shH,*shL,*ehH,*ehL,*dAH,*dAL,*ecH,*ecL,*t1H,*t1L;
    float *encpre,*decpre,*qkey,*qval,*ec,*dc,*akey;
    cudaGetSymbolAddress((void**)&WerH, g_WerH); cudaGetSymbolAddress((void**)&WerL, g_WerL);
    cudaGetSymbolAddress((void**)&WdrH, g_WdrH); cudaGetSymbolAddress((void**)&WdrL, g_WdrL);
    cudaGetSymbolAddress((void**)&WeiH, g_WeiH); cudaGetSymbolAddress((void**)&WeiL, g_WeiL);
    cudaGetSymbolAddress((void**)&WdiH, g_WdiH); cudaGetSymbolAddress((void**)&WdiL, g_WdiL);
    cudaGetSymbolAddress((void**)&WqkH, g_WqkH); cudaGetSymbolAddress((void**)&WqkL, g_WqkL);
    cudaGetSymbolAddress((void**)&WqvH, g_WqvH); cudaGetSymbolAddress((void**)&WqvL, g_WqvL);
    cudaGetSymbolAddress((void**)&WaH,  g_WaH ); cudaGetSymbolAddress((void**)&WaL,  g_WaL );
    cudaGetSymbolAddress((void**)&Wh1H, g_Wh1H); cudaGetSymbolAddress((void**)&Wh1L, g_Wh1L);
    cudaGetSymbolAddress((void**)&Wh2H, g_Wh2H); cudaGetSymbolAddress((void**)&Wh2L, g_Wh2L);
    cudaGetSymbolAddress((void**)&Wc1H, g_Wc1H); cudaGetSymbolAddress((void**)&Wc1L, g_Wc1L);
    cudaGetSymbolAddress((void**)&Wc2H, g_Wc2H); cudaGetSymbolAddress((void**)&Wc2L, g_Wc2L);
    cudaGetSymbolAddress((void**)&seH, g_seH); cudaGetSymbolAddress((void**)&seL, g_seL);
    cudaGetSymbolAddress((void**)&aeH, g_aeH); cudaGetSymbolAddress((void**)&aeL, g_aeL);
    cudaGetSymbolAddress((void**)&shH, g_shH); cudaGetSymbolAddress((void**)&shL, g_shL);
    cudaGetSymbolAddress((void**)&ehH, g_ehH); cudaGetSymbolAddress((void**)&ehL, g_ehL);
    cudaGetSymbolAddress((void**)&dAH, g_dAH); cudaGetSymbolAddress((void**)&dAL, g_dAL);
    cudaGetSymbolAddress((void**)&ecH, g_ecH); cudaGetSymbolAddress((void**)&ecL, g_ecL);
    cudaGetSymbolAddress((void**)&t1H, g_t1H); cudaGetSymbolAddress((void**)&t1L, g_t1L);
    cudaGetSymbolAddress((void**)&encpre, g_encpre); cudaGetSymbolAddress((void**)&decpre, g_decpre);
    cudaGetSymbolAddress((void**)&qkey, g_qkey); cudaGetSymbolAddress((void**)&qval, g_qval);
    cudaGetSymbolAddress((void**)&ec, g_ec); cudaGetSymbolAddress((void**)&dc, g_dc);
    cudaGetSymbolAddress((void**)&akey, g_akey);

    // ---- setup: weight conversions + gathers ----
    convw_kernel<<<1024, 256>>>(WerH, WerL, enc_Whh, nullptr, 4096, 0, KE, 1024, 1024, 1);
    convw_kernel<<<1024, 256>>>(WdrH, WdrL, dec_Whh, dec_Wih, 4096, 0, KDR, 1324, 0, 2);
    convw_kernel<<<1024, 256>>>(WeiH, WeiL, enc_Wih, nullptr, 4096, 0, KSE, 300, 300, 1);
    convw_kernel<<<1024, 256>>>(WdiH, WdiL, dec_Wih, nullptr, 4096, 0, KAE, 556, 856, 1);
    convw_kernel<<<256, 256>>>(WqkH, WqkL, Wqk, nullptr, 128, 100, 1024, 1024, 1024, 0);
    convw_kernel<<<256, 256>>>(WqvH, WqvL, Wqv, nullptr, 320, 300, 1024, 1024, 1024, 0);
    convw_kernel<<<256, 256>>>(WaH,  WaL,  Wa,  nullptr, 128, 100, 1024, 1024, 1024, 0);
    convw_kernel<<<1024, 256>>>(Wh1H, Wh1L, Wh1, nullptr, 2048, 2048, 1024, 1024, 1024, 0);
    convw_kernel<<<1024, 256>>>(Wh2H, Wh2L, Wh2, nullptr, 1024, 1024, 2048, 2048, 2048, 0);
    convw_kernel<<<1024, 256>>>(Wc1H, Wc1L, Wc1, nullptr, 2048, 2048, 1024, 1024, 1024, 0);
    convw_kernel<<<1024, 256>>>(Wc2H, Wc2L, Wc2, nullptr, 1024, 1024, 2048, 2048, 2048, 0);
    gather_kernel<<<2048, 256>>>(src_seqs, trg_nt, par_nt, par_lex, lex_emb, nt_emb);

    // ---- input-side precompute (packed-n fp32 outputs) ----
    mma_gemm<0,0><<<dim3(128,128), 256, SMEMB>>>(seH, seL, KSE, WeiH, WeiL, KSE, 4096, KSE/64,
        nullptr, nullptr, encpre, nullptr, nullptr, 4096,
        nullptr, 0, nullptr, nullptr, 0, nullptr, nullptr, nullptr, nullptr);
    mma_gemm<0,0><<<dim3(128,64), 256, SMEMB>>>(aeH, aeL, KAE, WdiH, WdiL, KAE, 4096, KAE/64,
        nullptr, nullptr, decpre, nullptr, nullptr, 4096,
        nullptr, 0, nullptr, nullptr, 0, nullptr, nullptr, nullptr, nullptr);

    // ---- encoder recurrence ----
    for (int s = 0; s < S_SRC; s++) {
        int p = s & 1;
        mma_gemm<2,0><<<dim3(128,1), 256, SMEMB>>>(ehH + p*B*H, ehL + p*B*H, H,
            WerH, WerL, KE, 4096, KE/64,
            enc_b, encpre + (int64_t)s*B*4096, nullptr, nullptr, nullptr, 0,
            src_len, s, ehH + (p^1)*B*H, ehL + (p^1)*B*H, H, ec, shH, shL, nullptr);
    }
    __nv_bfloat16* ehTH = ehH + (S_SRC & 1) * B * H;
    __nv_bfloat16* ehTL = ehL + (S_SRC & 1) * B * H;

    // ---- attention keys/values (batched over all positions) ----
    mma_gemm<0,2><<<dim3(4,128), 256, SMEMB>>>(shH, shL, H, WqkH, WqkL, 1024, 100, 16,
        bqk, nullptr, qkey, nullptr, nullptr, 112,
        nullptr, 0, nullptr, nullptr, 0, nullptr, nullptr, nullptr, nullptr);
    mma_gemm<0,0><<<dim3(10,128), 256, SMEMB>>>(shH, shL, H, WqvH, WqvL, 1024, 300, 16,
        bqv, nullptr, qval, nullptr, nullptr, 304,
        nullptr, 0, nullptr, nullptr, 0, nullptr, nullptr, nullptr, nullptr);

    // ---- decoder init MLPs ----
    convw_kernel<<<256, 256>>>(ecH, ecL, ec, nullptr, 128, 128, 1024, 1024, 1024, 0);
    mma_gemm<1,1><<<dim3(64,1), 256, SMEMB>>>(ehTH, ehTL, H, Wh1H, Wh1L, 1024, 2048, 16,
        bh1, nullptr, nullptr, t1H, t1L, 2048,
        nullptr, 0, nullptr, nullptr, 0, nullptr, nullptr, nullptr, nullptr);
    mma_gemm<1,0><<<dim3(32,1), 256, SMEMB>>>(t1H, t1L, 2048, Wh2H, Wh2L, 2048, 1024, 32,
        bh2, nullptr, nullptr, dAH, dAL, KDR,
        nullptr, 0, nullptr, nullptr, 0, nullptr, nullptr, nullptr, nullptr);
    mma_gemm<1,1><<<dim3(64,1), 256, SMEMB>>>(ecH, ecL, H, Wc1H, Wc1L, 1024, 2048, 16,
        bc1, nullptr, nullptr, t1H, t1L, 2048,
        nullptr, 0, nullptr, nullptr, 0, nullptr, nullptr, nullptr, nullptr);
    mma_gemm<0,0><<<dim3(32,1), 256, SMEMB>>>(t1H, t1L, 2048, Wc2H, Wc2L, 2048, 1024, 32,
        bc2, nullptr, dc, nullptr, nullptr, 1024,
        nullptr, 0, nullptr, nullptr, 0, nullptr, nullptr, nullptr, nullptr);

    // ---- decoder recurrence with attention ----
    for (int t = 0; t < S_TRG; t++) {
        int p = t & 1;
        mma_gemm<0,2><<<dim3(4,1), 256, SMEMB>>>(dAH + p*B*KDR, dAL + p*B*KDR, KDR,
            WaH, WaL, 1024, 100, 16,
            ba, nullptr, akey, nullptr, nullptr, 112,
            nullptr, 0, nullptr, nullptr, 0, nullptr, nullptr, nullptr, nullptr);
        attn2_kernel<<<128, 128>>>(src_len, dAH + p*B*KDR, dAL + p*B*KDR);
        mma_gemm<3,0><<<dim3(128,1), 256, SMEMB>>>(dAH + p*B*KDR, dAL + p*B*KDR, KDR,
            WdrH, WdrL, KDR, 4096, KDR/64,
            dec_b, decpre + (int64_t)t*B*4096, nullptr, nullptr, nullptr, 0,
            src_len, t, dAH + (p^1)*B*KDR, dAL + (p^1)*B*KDR, KDR, dc, nullptr, nullptr, out);
    }
}